// round 1
// baseline (speedup 1.0000x reference)
#include <cuda_runtime.h>
#include <math.h>

#define BATCH 64
#define NPTS 2048
#define KDIM 98304          // 2048*48
#define NCLS 1000
#define KCHUNKS 24
#define KC (KDIM / KCHUNKS) // 4096
#define KB 16
#define TN 64

// Scratch (device globals: allocation-free rule)
__device__ float g_xy[NPTS * BATCH * 2];             // [(p*64+b)*2 + {x,y}]
__device__ float g_P[(size_t)KDIM * BATCH];          // k-major: P[k*64 + b], 25 MB
__device__ float g_part[(size_t)KCHUNKS * BATCH * NCLS]; // split-K partials, 6.1 MB

// ---------------------------------------------------------------------------
// Kernel 1: tv resize (degenerate: avg of 4 pixels) + 48x4096 GEMM + sigmoid
// -> scaled coords. One CTA per batch element.
// ---------------------------------------------------------------------------
__global__ void k_coords(const float* __restrict__ tv_img,
                         const float* __restrict__ w1,
                         const float* __restrict__ b1) {
    int b = blockIdx.x;
    int tid = threadIdx.x;
    __shared__ float tv[48];
    if (tid < 48) {
        int c = tid / 16, rem = tid % 16, i = rem / 4, j = rem % 4;
        const float* base = tv_img + ((size_t)(b * 3 + c)) * 64 * 64;
        int r0 = 16 * i + 7, c0 = 16 * j + 7;
        tv[tid] = 0.25f * (base[r0 * 64 + c0] + base[r0 * 64 + c0 + 1] +
                           base[(r0 + 1) * 64 + c0] + base[(r0 + 1) * 64 + c0 + 1]);
    }
    __syncthreads();
    for (int m = tid; m < 4096; m += blockDim.x) {
        float acc = b1[m];
#pragma unroll
        for (int d = 0; d < 48; d++) acc += tv[d] * w1[d * 4096 + m];
        float s = 1.0f / (1.0f + expf(-acc));
        // xs = s*(H-1-PATCH) + PATCH/2 = s*1019 + 2  (same for ys, H==W)
        float coord = s * 1019.0f + 2.0f;
        int p = m >> 1, q = m & 1;
        g_xy[(p * BATCH + b) * 2 + q] = coord;
    }
}

// ---------------------------------------------------------------------------
// Kernel 2: bilinear patch gather into k-major P.
// patch[i][j][ch] = bilinear(img_b, x+i-2, y+j-2)[ch]
// block: (64 batch, 4 ij), grid: (2048 p, 4 ij-groups)
// ---------------------------------------------------------------------------
__global__ void k_gather(const float* __restrict__ img) {
    int b  = threadIdx.x;                       // 0..63
    int p  = blockIdx.x;                        // 0..2047
    int ij = blockIdx.y * blockDim.y + threadIdx.y; // 0..15
    float x = g_xy[(p * BATCH + b) * 2 + 0];
    float y = g_xy[(p * BATCH + b) * 2 + 1];
    float x0 = floorf(x), y0 = floorf(y);
    float fx = x - x0, fy = y - y0;
    int ix = (int)x0, iy = (int)y0;
    int i = ij >> 2, j = ij & 3;
    int r = ix + i - 2, c = iy + j - 2;
    const float* ib  = img + (size_t)b * (1024u * 1024u * 3u);
    const float* p00 = ib + ((size_t)r * 1024 + c) * 3;
    const float* p01 = p00 + 3;
    const float* p10 = p00 + 1024 * 3;
    const float* p11 = p10 + 3;
    float w00 = (1.0f - fx) * (1.0f - fy);
    float w01 = (1.0f - fx) * fy;
    float w10 = fx * (1.0f - fy);
    float w11 = fx * fy;
    int kbase = p * 48 + ij * 3;
#pragma unroll
    for (int ch = 0; ch < 3; ch++) {
        float v = p00[ch] * w00 + p01[ch] * w01 + p10[ch] * w10 + p11[ch] * w11;
        g_P[(size_t)(kbase + ch) * BATCH + b] = v;   // coalesced over b
    }
}

// ---------------------------------------------------------------------------
// Kernel 3: split-K fp32 SIMT GEMM. Grid (16 n-tiles, 24 k-chunks), 256 thr.
// CTA computes 64x64 tile over KC=4096, writes partials (deterministic).
// ---------------------------------------------------------------------------
__global__ void __launch_bounds__(256) k_gemm(const float* __restrict__ w2) {
    int n0 = blockIdx.x * TN;
    int kchunk = blockIdx.y;
    int k0 = kchunk * KC;

    __shared__ float As[KB][64];
    __shared__ float Bs[KB][TN];

    int tid = threadIdx.x;
    int tx = tid & 15, ty = tid >> 4;
    int lrow = tid >> 4;          // 0..15
    int lcol4 = (tid & 15) * 4;   // 0,4,...,60

    float acc[4][4] = {};

    for (int k = k0; k < k0 + KC; k += KB) {
        // A tile: 16 rows of 64 batch values, float4 coalesced
        float4 a4 = *(const float4*)(&g_P[(size_t)(k + lrow) * BATCH + lcol4]);
        *(float4*)&As[lrow][lcol4] = a4;
        // B tile: guarded scalar loads (n may exceed 999 in last tile)
#pragma unroll
        for (int u = 0; u < 4; u++) {
            int n = n0 + lcol4 + u;
            Bs[lrow][lcol4 + u] = (n < NCLS) ? w2[(size_t)(k + lrow) * NCLS + n] : 0.0f;
        }
        __syncthreads();
#pragma unroll
        for (int kk = 0; kk < KB; kk++) {
            float4 av = *(const float4*)&As[kk][ty * 4];
            float4 bv = *(const float4*)&Bs[kk][tx * 4];
            float a[4] = {av.x, av.y, av.z, av.w};
            float bb[4] = {bv.x, bv.y, bv.z, bv.w};
#pragma unroll
            for (int r = 0; r < 4; r++)
#pragma unroll
                for (int c = 0; c < 4; c++)
                    acc[r][c] += a[r] * bb[c];
        }
        __syncthreads();
    }

    float* part = &g_part[(size_t)kchunk * (BATCH * NCLS)];
#pragma unroll
    for (int r = 0; r < 4; r++) {
        int m = ty * 4 + r;
#pragma unroll
        for (int c = 0; c < 4; c++) {
            int n = n0 + tx * 4 + c;
            if (n < NCLS) part[m * NCLS + n] = acc[r][c];
        }
    }
}

// ---------------------------------------------------------------------------
// Kernel 4: reduce split-K partials + b2 -> out
// ---------------------------------------------------------------------------
__global__ void k_reduce(float* __restrict__ out, const float* __restrict__ b2) {
    int idx = blockIdx.x * blockDim.x + threadIdx.x;
    if (idx >= BATCH * NCLS) return;
    int n = idx % NCLS;
    float acc = b2[n];
#pragma unroll
    for (int c = 0; c < KCHUNKS; c++)
        acc += g_part[(size_t)c * (BATCH * NCLS) + idx];
    out[idx] = acc;
}

// ---------------------------------------------------------------------------
extern "C" void kernel_launch(void* const* d_in, const int* in_sizes, int n_in,
                              void* d_out, int out_size) {
    const float* topview = (const float*)d_in[0];  // (64,3,64,64)
    const float* search  = (const float*)d_in[1];  // (64,1024,1024,3)
    const float* w1      = (const float*)d_in[2];  // (48,4096)
    const float* b1      = (const float*)d_in[3];  // (4096)
    const float* w2      = (const float*)d_in[4];  // (98304,1000)
    const float* b2      = (const float*)d_in[5];  // (1000)
    float* out = (float*)d_out;                    // (64,1000)

    k_coords<<<BATCH, 256>>>(topview, w1, b1);
    k_gather<<<dim3(NPTS, 4), dim3(64, 4)>>>(search);
    k_gemm<<<dim3(16, KCHUNKS), 256>>>(w2);
    k_reduce<<<(BATCH * NCLS + 255) / 256, 256>>>(out, b2);
}

// round 3
// speedup vs baseline: 2.4389x; 2.4389x over previous
#include <cuda_runtime.h>
#include <cstdint>
#include <math.h>

#define BATCH 64
#define NPTS 2048
#define KDIM 98304            // 2048*48
#define NCLS 1000
#define NPAD 1024
#define KSPLITS 96
#define KSP (KDIM / KSPLITS)  // 1024
#define KB 32                 // K per stage
#define STAGES_PER_CTA (KSP / KB)  // 32
#define TN 256                // N per CTA
#define NSTAGES 4

// SMEM padded strides (conflict-free for mma fragment loads)
#define A_STRIDE 36           // floats per A row  -> bank (4m+k)%32 distinct
#define B_STRIDE 264          // floats per B row  -> bank (8k+n)%32 distinct
#define A_BYTES (64 * A_STRIDE * 4)        // 9216
#define B_BYTES (KB * B_STRIDE * 4)        // 33792
#define STAGE_BYTES (A_BYTES + B_BYTES)    // 43008
#define SMEM_DYN (NSTAGES * STAGE_BYTES)   // 172032

// ------------------------- device scratch -------------------------
__device__ float g_xy[BATCH * NPTS * 2];                     // [b][p][{x,y}]
__device__ __align__(16) float g_P[(size_t)BATCH * KDIM];    // row-major [64][98304]
__device__ float g_part[(size_t)KSPLITS * BATCH * NPAD];     // split-K partials, 25 MB

// ------------------------- helpers -------------------------
__device__ __forceinline__ uint32_t smem_u32(const void* p) {
    uint32_t a;
    asm("{ .reg .u64 t; cvta.to.shared.u64 t, %1; cvt.u32.u64 %0, t; }" : "=r"(a) : "l"(p));
    return a;
}
__device__ __forceinline__ void cp_async16(uint32_t dst, const void* src) {
    asm volatile("cp.async.cg.shared.global [%0], [%1], 16;" :: "r"(dst), "l"(src) : "memory");
}
__device__ __forceinline__ void cp_async16_sz(uint32_t dst, const void* src, uint32_t sz) {
    asm volatile("cp.async.cg.shared.global [%0], [%1], 16, %2;" :: "r"(dst), "l"(src), "r"(sz) : "memory");
}
__device__ __forceinline__ void cp_commit() { asm volatile("cp.async.commit_group;" ::: "memory"); }
__device__ __forceinline__ void cp_wait2()  { asm volatile("cp.async.wait_group 2;" ::: "memory"); }
__device__ __forceinline__ uint32_t f2tf32(float f) {
    uint32_t u;
    asm("cvt.rna.tf32.f32 %0, %1;" : "=r"(u) : "f"(f));
    return u;
}
__device__ __forceinline__ void mma_tf32(float* c, uint32_t a0, uint32_t a1, uint32_t a2,
                                         uint32_t a3, uint32_t b0, uint32_t b1) {
    asm volatile(
        "mma.sync.aligned.m16n8k8.row.col.f32.tf32.tf32.f32 "
        "{%0,%1,%2,%3}, {%4,%5,%6,%7}, {%8,%9}, {%0,%1,%2,%3};"
        : "+f"(c[0]), "+f"(c[1]), "+f"(c[2]), "+f"(c[3])
        : "r"(a0), "r"(a1), "r"(a2), "r"(a3), "r"(b0), "r"(b1));
}

// ---------------------------------------------------------------------------
// Kernel 1: tv resize (degenerate 4-pixel avg) + 48x4096 GEMM + sigmoid
// ---------------------------------------------------------------------------
__global__ void k_coords(const float* __restrict__ tv_img,
                         const float* __restrict__ w1,
                         const float* __restrict__ b1) {
    int b = blockIdx.x;
    int tid = threadIdx.x;
    __shared__ float tv[48];
    if (tid < 48) {
        int c = tid / 16, rem = tid % 16, i = rem / 4, j = rem % 4;
        const float* base = tv_img + ((size_t)(b * 3 + c)) * 64 * 64;
        int r0 = 16 * i + 7, c0 = 16 * j + 7;
        tv[tid] = 0.25f * (base[r0 * 64 + c0] + base[r0 * 64 + c0 + 1] +
                           base[(r0 + 1) * 64 + c0] + base[(r0 + 1) * 64 + c0 + 1]);
    }
    __syncthreads();
    for (int m = tid; m < 4096; m += blockDim.x) {
        float acc = b1[m];
#pragma unroll
        for (int d = 0; d < 48; d++) acc += tv[d] * w1[d * 4096 + m];
        float s = 1.0f / (1.0f + expf(-acc));
        float coord = s * 1019.0f + 2.0f;
        int p = m >> 1, q = m & 1;
        g_xy[(b * NPTS + p) * 2 + q] = coord;
    }
}

// ---------------------------------------------------------------------------
// Kernel 2: bilinear patch gather into row-major P[b][k]
// ---------------------------------------------------------------------------
__global__ void k_gather(const float* __restrict__ img) {
    int ij = threadIdx.x;                               // 0..15
    int p  = blockIdx.x * blockDim.y + threadIdx.y;     // 0..2047
    int b  = blockIdx.y;
    float x = g_xy[(b * NPTS + p) * 2 + 0];
    float y = g_xy[(b * NPTS + p) * 2 + 1];
    float x0 = floorf(x), y0 = floorf(y);
    float fx = x - x0, fy = y - y0;
    int ix = (int)x0, iy = (int)y0;
    int i = ij >> 2, j = ij & 3;
    int r = ix + i - 2, c = iy + j - 2;
    const float* ib  = img + (size_t)b * (1024u * 1024u * 3u);
    const float* p00 = ib + ((size_t)r * 1024 + c) * 3;
    const float* p01 = p00 + 3;
    const float* p10 = p00 + 1024 * 3;
    const float* p11 = p10 + 3;
    float w00 = (1.0f - fx) * (1.0f - fy);
    float w01 = (1.0f - fx) * fy;
    float w10 = fx * (1.0f - fy);
    float w11 = fx * fy;
    float* dst = &g_P[(size_t)b * KDIM + p * 48 + ij * 3];
#pragma unroll
    for (int ch = 0; ch < 3; ch++)
        dst[ch] = p00[ch] * w00 + p01[ch] * w01 + p10[ch] * w10 + p11[ch] * w11;
}

// ---------------------------------------------------------------------------
// Kernel 3: tf32 mma.sync split-K GEMM.
// Grid (4 N-tiles, 96 K-splits), 256 threads, 4-stage cp.async pipeline.
// CTA tile: M=64, N=256, K=32/stage. Warp grid 4x2, warp tile 16x128.
// ---------------------------------------------------------------------------
__global__ void __launch_bounds__(256) k_gemm(const float* __restrict__ w2) {
    extern __shared__ __align__(16) float smem[];
    const int tid = threadIdx.x;
    const int wid = tid >> 5;
    const int lane = tid & 31;
    const int n0 = blockIdx.x * TN;
    const int ksplit = blockIdx.y;
    const int k0 = ksplit * KSP;

    const int wm = wid >> 1;          // 0..3 -> m base = wm*16
    const int wn = wid & 1;           // 0..1 -> n base = wn*128
    const int g  = lane >> 2;         // group id 0..7
    const int t  = lane & 3;          // thread-in-group

    const uint32_t sbase = smem_u32(smem);

    // ---- load issue function (stage slot, k offset) ----
    auto issue_stage = [&](int slot, int kofs) {
        uint32_t st = sbase + slot * STAGE_BYTES;
        // A: 64 rows x 32 floats -> 512 chunks of 16B, 2 per thread
#pragma unroll
        for (int i = 0; i < 2; i++) {
            int c = tid + i * 256;
            int m = c >> 3, kc = (c & 7) * 4;
            cp_async16(st + m * (A_STRIDE * 4) + kc * 4,
                       &g_P[(size_t)m * KDIM + kofs + kc]);
        }
        // B: 32 rows x 256 floats -> 2048 chunks of 16B, 8 per thread
        uint32_t bb = st + A_BYTES;
#pragma unroll
        for (int i = 0; i < 8; i++) {
            int c = tid + i * 256;
            int k = c >> 6, nc = (c & 63) * 4;
            int n = n0 + nc;
            uint32_t sz = (n < NCLS) ? 16u : 0u;
            cp_async16_sz(bb + k * (B_STRIDE * 4) + nc * 4,
                          &w2[(size_t)(kofs + k) * NCLS + n], sz);
        }
        cp_commit();
    };

    // prologue: stages 0,1,2
#pragma unroll
    for (int s = 0; s < NSTAGES - 1; s++) issue_stage(s, k0 + s * KB);

    float acc[16][4];
#pragma unroll
    for (int j = 0; j < 16; j++)
#pragma unroll
        for (int r = 0; r < 4; r++) acc[j][r] = 0.0f;

    for (int s = 0; s < STAGES_PER_CTA; s++) {
        cp_wait2();
        __syncthreads();

        // issue stage s+3 into slot (s+3)%4 (== slot of stage s-1, all warps done with it)
        int sn = s + NSTAGES - 1;
        if (sn < STAGES_PER_CTA) issue_stage(sn & (NSTAGES - 1), k0 + sn * KB);
        else cp_commit();

        const float* As = smem + (s & (NSTAGES - 1)) * (STAGE_BYTES / 4);
        const float* Bs = As + A_BYTES / 4;
        const float* Arow = As + (wm * 16 + g) * A_STRIDE;

#pragma unroll
        for (int kk = 0; kk < 4; kk++) {
            int kb = kk * 8;
            uint32_t a0 = f2tf32(Arow[kb + t]);
            uint32_t a1 = f2tf32(Arow[8 * A_STRIDE + kb + t]);
            uint32_t a2 = f2tf32(Arow[kb + t + 4]);
            uint32_t a3 = f2tf32(Arow[8 * A_STRIDE + kb + t + 4]);
            const float* Bk0 = Bs + (kb + t) * B_STRIDE + wn * 128 + g;
            const float* Bk1 = Bk0 + 4 * B_STRIDE;
#pragma unroll
            for (int j = 0; j < 16; j++) {
                uint32_t b0 = f2tf32(Bk0[j * 8]);
                uint32_t b1 = f2tf32(Bk1[j * 8]);
                mma_tf32(acc[j], a0, a1, a2, a3, b0, b1);
            }
        }
        __syncthreads();
    }

    // ---- epilogue: write partials ----
    float* base = &g_part[(size_t)ksplit * BATCH * NPAD];
    int m_lo = wm * 16 + g;
#pragma unroll
    for (int j = 0; j < 16; j++) {
        int n = n0 + wn * 128 + j * 8 + 2 * t;
        float2 lo = make_float2(acc[j][0], acc[j][1]);
        float2 hi = make_float2(acc[j][2], acc[j][3]);
        *(float2*)&base[(size_t)m_lo * NPAD + n] = lo;
        *(float2*)&base[(size_t)(m_lo + 8) * NPAD + n] = hi;
    }
}

// ---------------------------------------------------------------------------
// Kernel 4: reduce split-K partials + b2 -> out
// ---------------------------------------------------------------------------
__global__ void k_reduce(float* __restrict__ out, const float* __restrict__ b2) {
    int idx = blockIdx.x * blockDim.x + threadIdx.x;
    if (idx >= BATCH * NCLS) return;
    int b = idx / NCLS, n = idx % NCLS;
    float acc = b2[n];
#pragma unroll
    for (int s = 0; s < KSPLITS; s++)
        acc += g_part[((size_t)s * BATCH + b) * NPAD + n];
    out[idx] = acc;
}

// ---------------------------------------------------------------------------
extern "C" void kernel_launch(void* const* d_in, const int* in_sizes, int n_in,
                              void* d_out, int out_size) {
    const float* topview = (const float*)d_in[0];  // (64,3,64,64)
    const float* search  = (const float*)d_in[1];  // (64,1024,1024,3)
    const float* w1      = (const float*)d_in[2];  // (48,4096)
    const float* b1      = (const float*)d_in[3];  // (4096)
    const float* w2      = (const float*)d_in[4];  // (98304,1000)
    const float* b2      = (const float*)d_in[5];  // (1000)
    float* out = (float*)d_out;                    // (64,1000)

    cudaFuncSetAttribute(k_gemm, cudaFuncAttributeMaxDynamicSharedMemorySize, SMEM_DYN);

    k_coords<<<BATCH, 256>>>(topview, w1, b1);
    k_gather<<<dim3(NPTS / 8, BATCH), dim3(16, 8)>>>(search);
    k_gemm<<<dim3(4, KSPLITS), 256, SMEM_DYN>>>(w2);
    k_reduce<<<(BATCH * NCLS + 255) / 256, 256>>>(out, b2);
}

// round 4
// speedup vs baseline: 2.5329x; 1.0385x over previous
#include <cuda_runtime.h>
#include <cstdint>
#include <math.h>

#define BATCH 64
#define NPTS 2048
#define KDIM 98304            // 2048*48
#define NCLS 1000
#define NPAD 1024
#define KSPLITS 96
#define KSP (KDIM / KSPLITS)  // 1024
#define KB 32                 // K per stage
#define STAGES_PER_CTA (KSP / KB)  // 32
#define TN 256                // N per CTA
#define NSTAGES 4

// SMEM padded strides
#define A_STRIDE 36           // floats per A row (LDS.128 conflict-free)
#define B_STRIDE 264          // floats per B row (scalar frag conflict-free)
#define A_BYTES (64 * A_STRIDE * 4)        // 9216
#define B_BYTES (KB * B_STRIDE * 4)        // 33792
#define STAGE_BYTES (A_BYTES + B_BYTES)    // 43008
#define SMEM_DYN (NSTAGES * STAGE_BYTES)   // 172032

// ------------------------- device scratch -------------------------
__device__ float g_xy[BATCH * NPTS * 2];                     // [b][p][{x,y}]
__device__ __align__(16) float g_P[(size_t)BATCH * KDIM];    // [64][98304], k-permuted, tf32-rounded
__device__ float g_part[(size_t)KSPLITS * BATCH * NPAD];     // split-K partials

// ------------------------- helpers -------------------------
__device__ __forceinline__ uint32_t smem_u32(const void* p) {
    uint32_t a;
    asm("{ .reg .u64 t; cvta.to.shared.u64 t, %1; cvt.u32.u64 %0, t; }" : "=r"(a) : "l"(p));
    return a;
}
__device__ __forceinline__ void cp_async16(uint32_t dst, const void* src) {
    asm volatile("cp.async.cg.shared.global [%0], [%1], 16;" :: "r"(dst), "l"(src) : "memory");
}
__device__ __forceinline__ void cp_async16_sz(uint32_t dst, const void* src, uint32_t sz) {
    asm volatile("cp.async.cg.shared.global [%0], [%1], 16, %2;" :: "r"(dst), "l"(src), "r"(sz) : "memory");
}
__device__ __forceinline__ void cp_commit() { asm volatile("cp.async.commit_group;" ::: "memory"); }
__device__ __forceinline__ void cp_wait2()  { asm volatile("cp.async.wait_group 2;" ::: "memory"); }
__device__ __forceinline__ float f2tf32_f(float f) {
    uint32_t u;
    asm("cvt.rna.tf32.f32 %0, %1;" : "=r"(u) : "f"(f));
    return __uint_as_float(u);
}
__device__ __forceinline__ uint32_t f2tf32(float f) {
    uint32_t u;
    asm("cvt.rna.tf32.f32 %0, %1;" : "=r"(u) : "f"(f));
    return u;
}
__device__ __forceinline__ void mma_tf32(float* c, uint32_t a0, uint32_t a1, uint32_t a2,
                                         uint32_t a3, uint32_t b0, uint32_t b1) {
    asm volatile(
        "mma.sync.aligned.m16n8k8.row.col.f32.tf32.tf32.f32 "
        "{%0,%1,%2,%3}, {%4,%5,%6,%7}, {%8,%9}, {%0,%1,%2,%3};"
        : "+f"(c[0]), "+f"(c[1]), "+f"(c[2]), "+f"(c[3])
        : "r"(a0), "r"(a1), "r"(a2), "r"(a3), "r"(b0), "r"(b1));
}

// ---------------------------------------------------------------------------
// Kernel 1: tv resize (degenerate 4-pixel avg) + 48x4096 GEMM + sigmoid
// ---------------------------------------------------------------------------
__global__ void k_coords(const float* __restrict__ tv_img,
                         const float* __restrict__ w1,
                         const float* __restrict__ b1) {
    int b = blockIdx.x;
    int tid = threadIdx.x;
    __shared__ float tv[48];
    if (tid < 48) {
        int c = tid / 16, rem = tid % 16, i = rem / 4, j = rem % 4;
        const float* base = tv_img + ((size_t)(b * 3 + c)) * 64 * 64;
        int r0 = 16 * i + 7, c0 = 16 * j + 7;
        tv[tid] = 0.25f * (base[r0 * 64 + c0] + base[r0 * 64 + c0 + 1] +
                           base[(r0 + 1) * 64 + c0] + base[(r0 + 1) * 64 + c0 + 1]);
    }
    __syncthreads();
    for (int m = tid; m < 4096; m += blockDim.x) {
        float acc = b1[m];
#pragma unroll
        for (int d = 0; d < 48; d++) acc += tv[d] * w1[d * 4096 + m];
        float s = 1.0f / (1.0f + expf(-acc));
        float coord = s * 1019.0f + 2.0f;
        int p = m >> 1, q = m & 1;
        g_xy[(b * NPTS + p) * 2 + q] = coord;
    }
}

// ---------------------------------------------------------------------------
// Kernel 2: bilinear patch gather -> g_P, tf32-rounded, k-permuted per 32-block
// perm(off) = (off%4)*8 + off/4   (so k == t (mod 4) values are contiguous)
// ---------------------------------------------------------------------------
__global__ void k_gather(const float* __restrict__ img) {
    int ij = threadIdx.x;                               // 0..15
    int p  = blockIdx.x * blockDim.y + threadIdx.y;     // 0..2047
    int b  = blockIdx.y;
    float x = g_xy[(b * NPTS + p) * 2 + 0];
    float y = g_xy[(b * NPTS + p) * 2 + 1];
    float x0 = floorf(x), y0 = floorf(y);
    float fx = x - x0, fy = y - y0;
    int ix = (int)x0, iy = (int)y0;
    int i = ij >> 2, j = ij & 3;
    int r = ix + i - 2, c = iy + j - 2;
    const float* ib  = img + (size_t)b * (1024u * 1024u * 3u);
    const float* p00 = ib + ((size_t)r * 1024 + c) * 3;
    const float* p01 = p00 + 3;
    const float* p10 = p00 + 1024 * 3;
    const float* p11 = p10 + 3;
    float w00 = (1.0f - fx) * (1.0f - fy);
    float w01 = (1.0f - fx) * fy;
    float w10 = fx * (1.0f - fy);
    float w11 = fx * fy;
    float* rowp = &g_P[(size_t)b * KDIM];
#pragma unroll
    for (int ch = 0; ch < 3; ch++) {
        float v = p00[ch] * w00 + p01[ch] * w01 + p10[ch] * w10 + p11[ch] * w11;
        int k = p * 48 + ij * 3 + ch;
        int off = k & 31;
        int kperm = (k & ~31) | ((off & 3) << 3) | (off >> 2);
        rowp[kperm] = f2tf32_f(v);
    }
}

// ---------------------------------------------------------------------------
// Kernel 3: tf32 mma.sync split-K GEMM.
// Grid (4 N-tiles, 96 K-splits), 256 threads, 4-stage cp.async pipeline.
// CTA tile: M=64, N=256, K=32/stage. Warp grid 1x8, warp tile m64 x n32.
// A fragments via LDS.128 (k-permuted), no cvt (pre-rounded in g_P).
// ---------------------------------------------------------------------------
__global__ void __launch_bounds__(256, 1) k_gemm(const float* __restrict__ w2) {
    extern __shared__ __align__(16) float smem[];
    const int tid = threadIdx.x;
    const int wid = tid >> 5;         // 0..7 -> n base = wid*32
    const int lane = tid & 31;
    const int n0 = blockIdx.x * TN;
    const int ksplit = blockIdx.y;
    const int k0 = ksplit * KSP;

    const int g  = lane >> 2;         // 0..7
    const int t  = lane & 3;          // 0..3

    const uint32_t sbase = smem_u32(smem);

    auto issue_stage = [&](int slot, int kofs) {
        uint32_t st = sbase + slot * STAGE_BYTES;
        // A: 64 rows x 32 floats -> 512 x 16B chunks, 2 per thread
#pragma unroll
        for (int i = 0; i < 2; i++) {
            int c = tid + i * 256;
            int m = c >> 3, kc = (c & 7) * 4;
            cp_async16(st + m * (A_STRIDE * 4) + kc * 4,
                       &g_P[(size_t)m * KDIM + kofs + kc]);
        }
        // B: 32 rows x 256 floats -> 2048 x 16B chunks, 8 per thread
        uint32_t bb = st + A_BYTES;
#pragma unroll
        for (int i = 0; i < 8; i++) {
            int c = tid + i * 256;
            int k = c >> 6, nc = (c & 63) * 4;
            int n = n0 + nc;
            uint32_t sz = (n < NCLS) ? 16u : 0u;
            cp_async16_sz(bb + k * (B_STRIDE * 4) + nc * 4,
                          &w2[(size_t)(kofs + k) * NCLS + n], sz);
        }
        cp_commit();
    };

#pragma unroll
    for (int s = 0; s < NSTAGES - 1; s++) issue_stage(s, k0 + s * KB);

    float acc[16][4];   // [mt*4 + nt][4]
#pragma unroll
    for (int j = 0; j < 16; j++)
#pragma unroll
        for (int r = 0; r < 4; r++) acc[j][r] = 0.0f;

    for (int s = 0; s < STAGES_PER_CTA; s++) {
        cp_wait2();
        __syncthreads();

        int sn = s + NSTAGES - 1;
        if (sn < STAGES_PER_CTA) issue_stage(sn & (NSTAGES - 1), k0 + sn * KB);
        else cp_commit();

        const float* As = smem + (s & (NSTAGES - 1)) * (STAGE_BYTES / 4);
        const float* Bs = As + A_BYTES / 4;

#pragma unroll
        for (int half = 0; half < 2; half++) {
            // A vectors: 8 rows (g + 8*jr), cols t*8 + half*4 .. +3
            // vector comps = k: half*16 + {t, t+4, t+8, t+12}
            float4 av[8];
#pragma unroll
            for (int jr = 0; jr < 8; jr++)
                av[jr] = *(const float4*)&As[(jr * 8 + g) * A_STRIDE + t * 8 + half * 4];

#pragma unroll
            for (int kk = 0; kk < 2; kk++) {            // kb = half*16 + kk*8
                int kb = half * 16 + kk * 8;
                const float* Bk0 = Bs + (kb + t) * B_STRIDE + wid * 32 + g;
                const float* Bk1 = Bk0 + 4 * B_STRIDE;
#pragma unroll
                for (int nt = 0; nt < 4; nt++) {
                    uint32_t b0 = f2tf32(Bk0[nt * 8]);
                    uint32_t b1 = f2tf32(Bk1[nt * 8]);
#pragma unroll
                    for (int mt = 0; mt < 4; mt++) {
                        // a0: row mt*16+g, k=kb+t ; a1: row mt*16+8+g ; a2/a3: k+4
                        float4 lo = av[2 * mt];       // row mt*16+g
                        float4 hi = av[2 * mt + 1];   // row mt*16+8+g
                        uint32_t a0 = __float_as_uint(kk ? lo.z : lo.x);
                        uint32_t a2 = __float_as_uint(kk ? lo.w : lo.y);
                        uint32_t a1 = __float_as_uint(kk ? hi.z : hi.x);
                        uint32_t a3 = __float_as_uint(kk ? hi.w : hi.y);
                        mma_tf32(acc[mt * 4 + nt], a0, a1, a2, a3, b0, b1);
                    }
                }
            }
        }
        __syncthreads();
    }

    // ---- epilogue: write partials ----
    float* base = &g_part[(size_t)ksplit * BATCH * NPAD];
#pragma unroll
    for (int mt = 0; mt < 4; mt++) {
#pragma unroll
        for (int nt = 0; nt < 4; nt++) {
            int m = mt * 16 + g;
            int n = n0 + wid * 32 + nt * 8 + 2 * t;
            float* a = acc[mt * 4 + nt];
            *(float2*)&base[(size_t)m * NPAD + n] = make_float2(a[0], a[1]);
            *(float2*)&base[(size_t)(m + 8) * NPAD + n] = make_float2(a[2], a[3]);
        }
    }
}

// ---------------------------------------------------------------------------
// Kernel 4: reduce split-K partials + b2 -> out
// ---------------------------------------------------------------------------
__global__ void k_reduce(float* __restrict__ out, const float* __restrict__ b2) {
    int idx = blockIdx.x * blockDim.x + threadIdx.x;
    if (idx >= BATCH * NCLS) return;
    int b = idx / NCLS, n = idx % NCLS;
    float acc = b2[n];
#pragma unroll
    for (int s = 0; s < KSPLITS; s++)
        acc += g_part[((size_t)s * BATCH + b) * NPAD + n];
    out[idx] = acc;
}

// ---------------------------------------------------------------------------
extern "C" void kernel_launch(void* const* d_in, const int* in_sizes, int n_in,
                              void* d_out, int out_size) {
    const float* topview = (const float*)d_in[0];  // (64,3,64,64)
    const float* search  = (const float*)d_in[1];  // (64,1024,1024,3)
    const float* w1      = (const float*)d_in[2];  // (48,4096)
    const float* b1      = (const float*)d_in[3];  // (4096)
    const float* w2      = (const float*)d_in[4];  // (98304,1000)
    const float* b2      = (const float*)d_in[5];  // (1000)
    float* out = (float*)d_out;                    // (64,1000)

    cudaFuncSetAttribute(k_gemm, cudaFuncAttributeMaxDynamicSharedMemorySize, SMEM_DYN);

    k_coords<<<BATCH, 256>>>(topview, w1, b1);
    k_gather<<<dim3(NPTS / 8, BATCH), dim3(16, 8)>>>(search);
    k_gemm<<<dim3(4, KSPLITS), 256, SMEM_DYN>>>(w2);
    k_reduce<<<(BATCH * NCLS + 255) / 256, 256>>>(out, b2);
}

// round 5
// speedup vs baseline: 2.5355x; 1.0010x over previous
#include <cuda_runtime.h>
#include <cstdint>
#include <math.h>

#define BATCH 64
#define NPTS 2048
#define KDIM 98304            // 2048*48
#define NCLS 1000
#define NPAD 1024
#define KSPLITS 96
#define KSP (KDIM / KSPLITS)  // 1024
#define KB 32                 // K per stage
#define STAGES_PER_CTA (KSP / KB)  // 32
#define TN 256                // N per CTA
#define NSTAGES 4

// SMEM padded strides
#define A_STRIDE 36           // floats per A row (LDS.128 conflict-free)
#define B_STRIDE 264          // floats per B row (scalar frag conflict-free)
#define A_BYTES (64 * A_STRIDE * 4)        // 9216
#define B_BYTES (KB * B_STRIDE * 4)        // 33792
#define STAGE_BYTES (A_BYTES + B_BYTES)    // 43008
#define SMEM_DYN (NSTAGES * STAGE_BYTES)   // 172032

// ------------------------- device scratch -------------------------
__device__ float g_xy[BATCH * NPTS * 2];                     // [b][p][{x,y}]
__device__ __align__(16) float g_P[(size_t)BATCH * KDIM];    // [64][98304], k-permuted, tf32-rounded
__device__ float g_part[(size_t)KSPLITS * BATCH * NPAD];     // split-K partials

// ------------------------- helpers -------------------------
__device__ __forceinline__ uint32_t smem_u32(const void* p) {
    uint32_t a;
    asm("{ .reg .u64 t; cvta.to.shared.u64 t, %1; cvt.u32.u64 %0, t; }" : "=r"(a) : "l"(p));
    return a;
}
__device__ __forceinline__ void cp_async16(uint32_t dst, const void* src) {
    asm volatile("cp.async.cg.shared.global [%0], [%1], 16;" :: "r"(dst), "l"(src) : "memory");
}
__device__ __forceinline__ void cp_async16_sz(uint32_t dst, const void* src, uint32_t sz) {
    asm volatile("cp.async.cg.shared.global [%0], [%1], 16, %2;" :: "r"(dst), "l"(src), "r"(sz) : "memory");
}
__device__ __forceinline__ void cp_commit() { asm volatile("cp.async.commit_group;" ::: "memory"); }
__device__ __forceinline__ void cp_wait2()  { asm volatile("cp.async.wait_group 2;" ::: "memory"); }
__device__ __forceinline__ float f2tf32_f(float f) {
    uint32_t u;
    asm("cvt.rna.tf32.f32 %0, %1;" : "=r"(u) : "f"(f));
    return __uint_as_float(u);
}
__device__ __forceinline__ uint32_t f2tf32(float f) {
    uint32_t u;
    asm("cvt.rna.tf32.f32 %0, %1;" : "=r"(u) : "f"(f));
    return u;
}
__device__ __forceinline__ void mma_tf32(float* c, uint32_t a0, uint32_t a1, uint32_t a2,
                                         uint32_t a3, uint32_t b0, uint32_t b1) {
    asm volatile(
        "mma.sync.aligned.m16n8k8.row.col.f32.tf32.tf32.f32 "
        "{%0,%1,%2,%3}, {%4,%5,%6,%7}, {%8,%9}, {%0,%1,%2,%3};"
        : "+f"(c[0]), "+f"(c[1]), "+f"(c[2]), "+f"(c[3])
        : "r"(a0), "r"(a1), "r"(a2), "r"(a3), "r"(b0), "r"(b1));
}

// ---------------------------------------------------------------------------
// Kernel 1: tv resize (degenerate 4-pixel avg) + 48x4096 GEMM + sigmoid
// ---------------------------------------------------------------------------
__global__ void k_coords(const float* __restrict__ tv_img,
                         const float* __restrict__ w1,
                         const float* __restrict__ b1) {
    int b = blockIdx.x;
    int tid = threadIdx.x;
    __shared__ float tv[48];
    if (tid < 48) {
        int c = tid / 16, rem = tid % 16, i = rem / 4, j = rem % 4;
        const float* base = tv_img + ((size_t)(b * 3 + c)) * 64 * 64;
        int r0 = 16 * i + 7, c0 = 16 * j + 7;
        tv[tid] = 0.25f * (base[r0 * 64 + c0] + base[r0 * 64 + c0 + 1] +
                           base[(r0 + 1) * 64 + c0] + base[(r0 + 1) * 64 + c0 + 1]);
    }
    __syncthreads();
    for (int m = tid; m < 4096; m += blockDim.x) {
        float acc = b1[m];
#pragma unroll
        for (int d = 0; d < 48; d++) acc += tv[d] * w1[d * 4096 + m];
        float s = 1.0f / (1.0f + expf(-acc));
        float coord = s * 1019.0f + 2.0f;
        int p = m >> 1, q = m & 1;
        g_xy[(b * NPTS + p) * 2 + q] = coord;
    }
}

// ---------------------------------------------------------------------------
// Kernel 2: bilinear patch gather -> g_P, tf32-rounded, k-permuted per 32-block
// perm(off) = (off%4)*8 + off/4
// ---------------------------------------------------------------------------
__global__ void k_gather(const float* __restrict__ img) {
    int ij = threadIdx.x;                               // 0..15
    int p  = blockIdx.x * blockDim.y + threadIdx.y;     // 0..2047
    int b  = blockIdx.y;
    float x = g_xy[(b * NPTS + p) * 2 + 0];
    float y = g_xy[(b * NPTS + p) * 2 + 1];
    float x0 = floorf(x), y0 = floorf(y);
    float fx = x - x0, fy = y - y0;
    int ix = (int)x0, iy = (int)y0;
    int i = ij >> 2, j = ij & 3;
    int r = ix + i - 2, c = iy + j - 2;
    const float* ib  = img + (size_t)b * (1024u * 1024u * 3u);
    const float* p00 = ib + ((size_t)r * 1024 + c) * 3;
    const float* p01 = p00 + 3;
    const float* p10 = p00 + 1024 * 3;
    const float* p11 = p10 + 3;
    float w00 = (1.0f - fx) * (1.0f - fy);
    float w01 = (1.0f - fx) * fy;
    float w10 = fx * (1.0f - fy);
    float w11 = fx * fy;
    float* rowp = &g_P[(size_t)b * KDIM];
#pragma unroll
    for (int ch = 0; ch < 3; ch++) {
        float v = p00[ch] * w00 + p01[ch] * w01 + p10[ch] * w10 + p11[ch] * w11;
        int k = p * 48 + ij * 3 + ch;
        int off = k & 31;
        int kperm = (k & ~31) | ((off & 3) << 3) | (off >> 2);
        rowp[kperm] = f2tf32_f(v);
    }
}

// ---------------------------------------------------------------------------
// Kernel 3: tf32 mma.sync split-K GEMM.
// Grid (4 N-tiles, 96 K-splits), 256 threads, 4-stage cp.async pipeline.
// CTA tile: M=64, N=256, K=32/stage. Warp grid 1x8, warp tile m64 x n32.
// Stage compute: preload ALL 32 B fragments (+cvt), then uninterrupted
// 64-HMMA bursts per half -> no LDS/cvt between MMAs (ILP experiment).
// ---------------------------------------------------------------------------
__global__ void __launch_bounds__(256, 1) k_gemm(const float* __restrict__ w2) {
    extern __shared__ __align__(16) float smem[];
    const int tid = threadIdx.x;
    const int wid = tid >> 5;         // 0..7 -> n base = wid*32
    const int lane = tid & 31;
    const int n0 = blockIdx.x * TN;
    const int ksplit = blockIdx.y;
    const int k0 = ksplit * KSP;

    const int g  = lane >> 2;         // 0..7
    const int t  = lane & 3;          // 0..3

    const uint32_t sbase = smem_u32(smem);

    auto issue_stage = [&](int slot, int kofs) {
        uint32_t st = sbase + slot * STAGE_BYTES;
#pragma unroll
        for (int i = 0; i < 2; i++) {
            int c = tid + i * 256;
            int m = c >> 3, kc = (c & 7) * 4;
            cp_async16(st + m * (A_STRIDE * 4) + kc * 4,
                       &g_P[(size_t)m * KDIM + kofs + kc]);
        }
        uint32_t bb = st + A_BYTES;
#pragma unroll
        for (int i = 0; i < 8; i++) {
            int c = tid + i * 256;
            int k = c >> 6, nc = (c & 63) * 4;
            int n = n0 + nc;
            uint32_t sz = (n < NCLS) ? 16u : 0u;
            cp_async16_sz(bb + k * (B_STRIDE * 4) + nc * 4,
                          &w2[(size_t)(kofs + k) * NCLS + n], sz);
        }
        cp_commit();
    };

#pragma unroll
    for (int s = 0; s < NSTAGES - 1; s++) issue_stage(s, k0 + s * KB);

    float acc[16][4];   // [mt*4 + nt][4]
#pragma unroll
    for (int j = 0; j < 16; j++)
#pragma unroll
        for (int r = 0; r < 4; r++) acc[j][r] = 0.0f;

    for (int s = 0; s < STAGES_PER_CTA; s++) {
        cp_wait2();
        __syncthreads();

        int sn = s + NSTAGES - 1;
        if (sn < STAGES_PER_CTA) issue_stage(sn & (NSTAGES - 1), k0 + sn * KB);
        else cp_commit();

        const float* As = smem + (s & (NSTAGES - 1)) * (STAGE_BYTES / 4);
        const float* Bs = As + A_BYTES / 4;

        // ---- preload + convert ALL B fragments for this stage ----
        uint32_t bf[4][4][2];     // [kb][nt][{b0,b1}]
#pragma unroll
        for (int kb = 0; kb < 4; kb++) {
            const float* Bk = Bs + (kb * 8 + t) * B_STRIDE + wid * 32 + g;
#pragma unroll
            for (int nt = 0; nt < 4; nt++) {
                bf[kb][nt][0] = f2tf32(Bk[nt * 8]);
                bf[kb][nt][1] = f2tf32(Bk[4 * B_STRIDE + nt * 8]);
            }
        }

#pragma unroll
        for (int half = 0; half < 2; half++) {
            // A vectors: comps = k: half*16 + {t, t+4, t+8, t+12}
            float4 av[8];
#pragma unroll
            for (int jr = 0; jr < 8; jr++)
                av[jr] = *(const float4*)&As[(jr * 8 + g) * A_STRIDE + t * 8 + half * 4];

            // ---- uninterrupted HMMA burst: 32 mma per half ----
#pragma unroll
            for (int kk = 0; kk < 2; kk++) {
                int kb = half * 2 + kk;
#pragma unroll
                for (int nt = 0; nt < 4; nt++) {
                    uint32_t b0 = bf[kb][nt][0];
                    uint32_t b1 = bf[kb][nt][1];
#pragma unroll
                    for (int mt = 0; mt < 4; mt++) {
                        float4 lo = av[2 * mt];
                        float4 hi = av[2 * mt + 1];
                        uint32_t a0 = __float_as_uint(kk ? lo.z : lo.x);
                        uint32_t a2 = __float_as_uint(kk ? lo.w : lo.y);
                        uint32_t a1 = __float_as_uint(kk ? hi.z : hi.x);
                        uint32_t a3 = __float_as_uint(kk ? hi.w : hi.y);
                        mma_tf32(acc[mt * 4 + nt], a0, a1, a2, a3, b0, b1);
                    }
                }
            }
        }
        __syncthreads();
    }

    // ---- epilogue: write partials ----
    float* base = &g_part[(size_t)ksplit * BATCH * NPAD];
#pragma unroll
    for (int mt = 0; mt < 4; mt++) {
#pragma unroll
        for (int nt = 0; nt < 4; nt++) {
            int m = mt * 16 + g;
            int n = n0 + wid * 32 + nt * 8 + 2 * t;
            float* a = acc[mt * 4 + nt];
            *(float2*)&base[(size_t)m * NPAD + n] = make_float2(a[0], a[1]);
            *(float2*)&base[(size_t)(m + 8) * NPAD + n] = make_float2(a[2], a[3]);
        }
    }
}

// ---------------------------------------------------------------------------
// Kernel 4: reduce split-K partials + b2 -> out
// ---------------------------------------------------------------------------
__global__ void k_reduce(float* __restrict__ out, const float* __restrict__ b2) {
    int idx = blockIdx.x * blockDim.x + threadIdx.x;
    if (idx >= BATCH * NCLS) return;
    int b = idx / NCLS, n = idx % NCLS;
    float acc = b2[n];
#pragma unroll
    for (int s = 0; s < KSPLITS; s++)
        acc += g_part[((size_t)s * BATCH + b) * NPAD + n];
    out[idx] = acc;
}

// ---------------------------------------------------------------------------
extern "C" void kernel_launch(void* const* d_in, const int* in_sizes, int n_in,
                              void* d_out, int out_size) {
    const float* topview = (const float*)d_in[0];  // (64,3,64,64)
    const float* search  = (const float*)d_in[1];  // (64,1024,1024,3)
    const float* w1      = (const float*)d_in[2];  // (48,4096)
    const float* b1      = (const float*)d_in[3];  // (4096)
    const float* w2      = (const float*)d_in[4];  // (98304,1000)
    const float* b2      = (const float*)d_in[5];  // (1000)
    float* out = (float*)d_out;                    // (64,1000)

    cudaFuncSetAttribute(k_gemm, cudaFuncAttributeMaxDynamicSharedMemorySize, SMEM_DYN);

    k_coords<<<BATCH, 256>>>(topview, w1, b1);
    k_gather<<<dim3(NPTS / 8, BATCH), dim3(16, 8)>>>(search);
    k_gemm<<<dim3(4, KSPLITS), 256, SMEM_DYN>>>(w2);
    k_reduce<<<(BATCH * NCLS + 255) / 256, 256>>>(out, b2);
}

// round 6
// speedup vs baseline: 2.6128x; 1.0305x over previous
#include <cuda_runtime.h>
#include <cstdint>
#include <math.h>

#define BATCH 64
#define NPTS 2048
#define KDIM 98304            // 2048*48
#define NCLS 1000
#define NPAD 1024
#define KSPLITS 96
#define KSP (KDIM / KSPLITS)  // 1024
#define KB 32                 // K per stage
#define STAGES_PER_CTA (KSP / KB)  // 32
#define TN 256                // N per CTA
#define NSTAGES 2

// SMEM padded strides
#define A_STRIDE 36           // floats per A row
#define B_STRIDE 264          // floats per B row (scalar frag conflict-free)
#define A_BYTES (64 * A_STRIDE * 4)        // 9216
#define B_BYTES (KB * B_STRIDE * 4)        // 33792
#define STAGE_BYTES (A_BYTES + B_BYTES)    // 43008
#define SMEM_DYN (NSTAGES * STAGE_BYTES)   // 86016 -> 2 CTAs/SM

// ------------------------- device scratch -------------------------
__device__ float g_xy[BATCH * NPTS * 2];                     // [b][p][{x,y}]
__device__ __align__(16) float g_P[(size_t)BATCH * KDIM];    // [64][98304], k-permuted, tf32-rounded
__device__ float g_part[(size_t)KSPLITS * BATCH * NPAD];     // split-K partials

// ------------------------- helpers -------------------------
__device__ __forceinline__ uint32_t smem_u32(const void* p) {
    uint32_t a;
    asm("{ .reg .u64 t; cvta.to.shared.u64 t, %1; cvt.u32.u64 %0, t; }" : "=r"(a) : "l"(p));
    return a;
}
__device__ __forceinline__ void cp_async16(uint32_t dst, const void* src) {
    asm volatile("cp.async.cg.shared.global [%0], [%1], 16;" :: "r"(dst), "l"(src) : "memory");
}
__device__ __forceinline__ void cp_async16_sz(uint32_t dst, const void* src, uint32_t sz) {
    asm volatile("cp.async.cg.shared.global [%0], [%1], 16, %2;" :: "r"(dst), "l"(src), "r"(sz) : "memory");
}
__device__ __forceinline__ void cp_commit() { asm volatile("cp.async.commit_group;" ::: "memory"); }
__device__ __forceinline__ void cp_wait1()  { asm volatile("cp.async.wait_group 1;" ::: "memory"); }
__device__ __forceinline__ float f2tf32_f(float f) {
    uint32_t u;
    asm("cvt.rna.tf32.f32 %0, %1;" : "=r"(u) : "f"(f));
    return __uint_as_float(u);
}
__device__ __forceinline__ uint32_t f2tf32(float f) {
    uint32_t u;
    asm("cvt.rna.tf32.f32 %0, %1;" : "=r"(u) : "f"(f));
    return u;
}
__device__ __forceinline__ void mma_tf32(float* c, uint32_t a0, uint32_t a1, uint32_t a2,
                                         uint32_t a3, uint32_t b0, uint32_t b1) {
    asm volatile(
        "mma.sync.aligned.m16n8k8.row.col.f32.tf32.tf32.f32 "
        "{%0,%1,%2,%3}, {%4,%5,%6,%7}, {%8,%9}, {%0,%1,%2,%3};"
        : "+f"(c[0]), "+f"(c[1]), "+f"(c[2]), "+f"(c[3])
        : "r"(a0), "r"(a1), "r"(a2), "r"(a3), "r"(b0), "r"(b1));
}

// ---------------------------------------------------------------------------
// Kernel 1: tv resize (degenerate 4-pixel avg) + 48x4096 GEMM + sigmoid
// ---------------------------------------------------------------------------
__global__ void k_coords(const float* __restrict__ tv_img,
                         const float* __restrict__ w1,
                         const float* __restrict__ b1) {
    int b = blockIdx.x;
    int tid = threadIdx.x;
    __shared__ float tv[48];
    if (tid < 48) {
        int c = tid / 16, rem = tid % 16, i = rem / 4, j = rem % 4;
        const float* base = tv_img + ((size_t)(b * 3 + c)) * 64 * 64;
        int r0 = 16 * i + 7, c0 = 16 * j + 7;
        tv[tid] = 0.25f * (base[r0 * 64 + c0] + base[r0 * 64 + c0 + 1] +
                           base[(r0 + 1) * 64 + c0] + base[(r0 + 1) * 64 + c0 + 1]);
    }
    __syncthreads();
    for (int m = tid; m < 4096; m += blockDim.x) {
        float acc = b1[m];
#pragma unroll
        for (int d = 0; d < 48; d++) acc += tv[d] * w1[d * 4096 + m];
        float s = 1.0f / (1.0f + expf(-acc));
        float coord = s * 1019.0f + 2.0f;
        int p = m >> 1, q = m & 1;
        g_xy[(b * NPTS + p) * 2 + q] = coord;
    }
}

// ---------------------------------------------------------------------------
// Kernel 2: bilinear patch gather -> g_P, tf32-rounded, k-permuted per 32-block
// perm(off) = (off%4)*8 + off/4  (so k and k+4 are adjacent)
// ---------------------------------------------------------------------------
__global__ void k_gather(const float* __restrict__ img) {
    int ij = threadIdx.x;                               // 0..15
    int p  = blockIdx.x * blockDim.y + threadIdx.y;     // 0..2047
    int b  = blockIdx.y;
    float x = g_xy[(b * NPTS + p) * 2 + 0];
    float y = g_xy[(b * NPTS + p) * 2 + 1];
    float x0 = floorf(x), y0 = floorf(y);
    float fx = x - x0, fy = y - y0;
    int ix = (int)x0, iy = (int)y0;
    int i = ij >> 2, j = ij & 3;
    int r = ix + i - 2, c = iy + j - 2;
    const float* ib  = img + (size_t)b * (1024u * 1024u * 3u);
    const float* p00 = ib + ((size_t)r * 1024 + c) * 3;
    const float* p01 = p00 + 3;
    const float* p10 = p00 + 1024 * 3;
    const float* p11 = p10 + 3;
    float w00 = (1.0f - fx) * (1.0f - fy);
    float w01 = (1.0f - fx) * fy;
    float w10 = fx * (1.0f - fy);
    float w11 = fx * fy;
    float* rowp = &g_P[(size_t)b * KDIM];
#pragma unroll
    for (int ch = 0; ch < 3; ch++) {
        float v = p00[ch] * w00 + p01[ch] * w01 + p10[ch] * w10 + p11[ch] * w11;
        int k = p * 48 + ij * 3 + ch;
        int off = k & 31;
        int kperm = (k & ~31) | ((off & 3) << 3) | (off >> 2);
        rowp[kperm] = f2tf32_f(v);
    }
}

// ---------------------------------------------------------------------------
// Kernel 3: tf32 mma.sync split-K GEMM, 2 CTAs/SM.
// Grid (4 N-tiles, 96 K-splits), 256 threads, 2-stage cp.async pipeline.
// CTA tile: M=64, N=256, K=32/stage. Warp grid 1x8, warp tile m64 x n32.
// ---------------------------------------------------------------------------
__global__ void __launch_bounds__(256, 2) k_gemm(const float* __restrict__ w2) {
    extern __shared__ __align__(16) float smem[];
    const int tid = threadIdx.x;
    const int wid = tid >> 5;         // 0..7 -> n base = wid*32
    const int lane = tid & 31;
    const int n0 = blockIdx.x * TN;
    const int ksplit = blockIdx.y;
    const int k0 = ksplit * KSP;

    const int g  = lane >> 2;         // 0..7
    const int t  = lane & 3;          // 0..3

    const uint32_t sbase = smem_u32(smem);

    auto issue_stage = [&](int slot, int kofs) {
        uint32_t st = sbase + slot * STAGE_BYTES;
        // A: 64 rows x 32 floats -> 512 x 16B chunks, 2 per thread
#pragma unroll
        for (int i = 0; i < 2; i++) {
            int c = tid + i * 256;
            int m = c >> 3, kc = (c & 7) * 4;
            cp_async16(st + m * (A_STRIDE * 4) + kc * 4,
                       &g_P[(size_t)m * KDIM + kofs + kc]);
        }
        // B: 32 rows x 256 floats -> 2048 x 16B chunks, 8 per thread
        uint32_t bb = st + A_BYTES;
#pragma unroll
        for (int i = 0; i < 8; i++) {
            int c = tid + i * 256;
            int k = c >> 6, nc = (c & 63) * 4;
            int n = n0 + nc;
            uint32_t sz = (n < NCLS) ? 16u : 0u;
            cp_async16_sz(bb + k * (B_STRIDE * 4) + nc * 4,
                          &w2[(size_t)(kofs + k) * NCLS + n], sz);
        }
        cp_commit();
    };

    // prologue: stage 0
    issue_stage(0, k0);

    float acc[16][4];   // [mt*4 + nt][4]
#pragma unroll
    for (int j = 0; j < 16; j++)
#pragma unroll
        for (int r = 0; r < 4; r++) acc[j][r] = 0.0f;

    for (int s = 0; s < STAGES_PER_CTA; s++) {
        // issue next stage FIRST (into the other slot), then wait for stage s
        int sn = s + 1;
        if (sn < STAGES_PER_CTA) issue_stage(sn & 1, k0 + sn * KB);
        else cp_commit();          // empty group so wait_group 1 drains stage s
        cp_wait1();
        __syncthreads();

        const float* As = smem + (s & 1) * (STAGE_BYTES / 4);
        const float* Bs = As + A_BYTES / 4;

#pragma unroll
        for (int kb = 0; kb < 4; kb++) {          // k block of 8: k = kb*8 + {t, t+4}
            // A: permuted layout puts k=kb*8+t at pos t*8+2*kb, k+4 at +1
            float2 af[8];
#pragma unroll
            for (int jr = 0; jr < 8; jr++)
                af[jr] = *(const float2*)&As[(jr * 8 + g) * A_STRIDE + t * 8 + 2 * kb];

            const float* Bk0 = Bs + (kb * 8 + t) * B_STRIDE + wid * 32 + g;
            const float* Bk1 = Bk0 + 4 * B_STRIDE;
#pragma unroll
            for (int nt = 0; nt < 4; nt++) {
                uint32_t b0 = f2tf32(Bk0[nt * 8]);
                uint32_t b1 = f2tf32(Bk1[nt * 8]);
#pragma unroll
                for (int mt = 0; mt < 4; mt++) {
                    uint32_t a0 = __float_as_uint(af[2 * mt].x);      // row mt*16+g,   k
                    uint32_t a2 = __float_as_uint(af[2 * mt].y);      // row mt*16+g,   k+4
                    uint32_t a1 = __float_as_uint(af[2 * mt + 1].x);  // row mt*16+8+g, k
                    uint32_t a3 = __float_as_uint(af[2 * mt + 1].y);  // row mt*16+8+g, k+4
                    mma_tf32(acc[mt * 4 + nt], a0, a1, a2, a3, b0, b1);
                }
            }
        }
        __syncthreads();
    }

    // ---- epilogue: write partials ----
    float* base = &g_part[(size_t)ksplit * BATCH * NPAD];
#pragma unroll
    for (int mt = 0; mt < 4; mt++) {
#pragma unroll
        for (int nt = 0; nt < 4; nt++) {
            int m = mt * 16 + g;
            int n = n0 + wid * 32 + nt * 8 + 2 * t;
            float* a = acc[mt * 4 + nt];
            *(float2*)&base[(size_t)m * NPAD + n] = make_float2(a[0], a[1]);
            *(float2*)&base[(size_t)(m + 8) * NPAD + n] = make_float2(a[2], a[3]);
        }
    }
}

// ---------------------------------------------------------------------------
// Kernel 4: reduce split-K partials + b2 -> out
// ---------------------------------------------------------------------------
__global__ void k_reduce(float* __restrict__ out, const float* __restrict__ b2) {
    int idx = blockIdx.x * blockDim.x + threadIdx.x;
    if (idx >= BATCH * NCLS) return;
    int b = idx / NCLS, n = idx % NCLS;
    float acc = b2[n];
#pragma unroll
    for (int s = 0; s < KSPLITS; s++)
        acc += g_part[((size_t)s * BATCH + b) * NPAD + n];
    out[idx] = acc;
}

// ---------------------------------------------------------------------------
extern "C" void kernel_launch(void* const* d_in, const int* in_sizes, int n_in,
                              void* d_out, int out_size) {
    const float* topview = (const float*)d_in[0];  // (64,3,64,64)
    const float* search  = (const float*)d_in[1];  // (64,1024,1024,3)
    const float* w1      = (const float*)d_in[2];  // (48,4096)
    const float* b1      = (const float*)d_in[3];  // (4096)
    const float* w2      = (const float*)d_in[4];  // (98304,1000)
    const float* b2      = (const float*)d_in[5];  // (1000)
    float* out = (float*)d_out;                    // (64,1000)

    cudaFuncSetAttribute(k_gemm, cudaFuncAttributeMaxDynamicSharedMemorySize, SMEM_DYN);

    k_coords<<<BATCH, 256>>>(topview, w1, b1);
    k_gather<<<dim3(NPTS / 8, BATCH), dim3(16, 8)>>>(search);
    k_gemm<<<dim3(4, KSPLITS), 256, SMEM_DYN>>>(w2);
    k_reduce<<<(BATCH * NCLS + 255) / 256, 256>>>(out, b2);
}